// round 7
// baseline (speedup 1.0000x reference)
#include <cuda_runtime.h>
#include <math.h>

#define S_LEN 1024
#define BATCH 128
#define DIN 256
#define NQ 8
#define FAN 264       // DIN + NQ
#define NPX 32        // padded: 4 gates * 8 slots (5 used per gate)

// precomputed x-part of gate pre-activations, S-MAJOR padded: [s][b][32]
// slot layout per gate g: [g*8 + i], i=0..4 for q in {0,1,5,6,7}
__device__ float g_Px[S_LEN * BATCH * NPX];

#define FULLMASK 0xffffffffu
__device__ __forceinline__ float shfl(float v, int src) { return __shfl_sync(FULLMASK, v, src); }
__device__ __forceinline__ float shflx(float v, int m)  { return __shfl_xor_sync(FULLMASK, v, m); }

// Hardware tanh: single MUFU instruction (sm_75+).
__device__ __forceinline__ float ftanh(float v) {
    float r;
    asm("tanh.approx.f32 %0, %1;" : "=f"(r) : "f"(v));
    return r;
}

// ---------------------------------------------------------------------------
// Kernel 1: Px[s,b,g*8+qi] = x[s,b,:] . W_g[q,:256] + b_g[q], q in {0,1,5,6,7}
// block = 160 threads = 10 output-PAIRS x 16 k-parts; 4 rows per iteration.
// Each thread computes TWO outputs per x value -> 2 FMA per LDS (halves smem BW).
// ---------------------------------------------------------------------------
__global__ void __launch_bounds__(160) px_kernel(
    const float* __restrict__ x,
    const float* __restrict__ W0, const float* __restrict__ B0,
    const float* __restrict__ W1, const float* __restrict__ B1,
    const float* __restrict__ W2, const float* __restrict__ B2,
    const float* __restrict__ W3, const float* __restrict__ B3)
{
    __shared__ float xsh[4 * 256];
    const int t     = threadIdx.x;
    const int pairp = t >> 4;      // 0..9  -> outputs 2p, 2p+1
    const int part  = t & 15;      // k = jj*16 + part

    const int o0 = pairp * 2, o1 = o0 + 1;
    const int g0 = o0 / 5, qi0 = o0 % 5;
    const int g1 = o1 / 5, qi1 = o1 % 5;
    const int qmap[5] = {0, 1, 5, 6, 7};
    const int q0 = qmap[qi0], q1 = qmap[qi1];
    const int col0 = g0 * 8 + qi0, col1 = g1 * 8 + qi1;

    const float* Wp[4] = {W0, W1, W2, W3};
    const float* Bp[4] = {B0, B1, B2, B3};
    const float* Wr0 = Wp[g0] + q0 * FAN;
    const float* Wr1 = Wp[g1] + q1 * FAN;

    float w0[16], w1[16];
#pragma unroll
    for (int jj = 0; jj < 16; jj++) {
        w0[jj] = Wr0[jj * 16 + part];
        w1[jj] = Wr1[jj * 16 + part];
    }
    const float bias0 = Bp[g0][q0];
    const float bias1 = Bp[g1][q1];

    const int rpb   = (S_LEN * BATCH) / gridDim.x;
    const long base = (long)blockIdx.x * rpb;

    for (int r0 = 0; r0 < rpb; r0 += 4) {
        __syncthreads();
        const float4* src = (const float4*)(x + (base + r0) * DIN);
        for (int i = t; i < 256; i += 160) ((float4*)xsh)[i] = src[i];
        __syncthreads();

        float a00 = 0.f, a01 = 0.f, a02 = 0.f, a03 = 0.f;   // output o0, rows 0..3
        float a10 = 0.f, a11 = 0.f, a12 = 0.f, a13 = 0.f;   // output o1, rows 0..3
#pragma unroll
        for (int jj = 0; jj < 16; jj++) {
            const int k = jj * 16 + part;
            const float xv0 = xsh[k];
            const float xv1 = xsh[256 + k];
            const float xv2 = xsh[512 + k];
            const float xv3 = xsh[768 + k];
            a00 = fmaf(w0[jj], xv0, a00);  a10 = fmaf(w1[jj], xv0, a10);
            a01 = fmaf(w0[jj], xv1, a01);  a11 = fmaf(w1[jj], xv1, a11);
            a02 = fmaf(w0[jj], xv2, a02);  a12 = fmaf(w1[jj], xv2, a12);
            a03 = fmaf(w0[jj], xv3, a03);  a13 = fmaf(w1[jj], xv3, a13);
        }
#pragma unroll
        for (int m = 1; m < 16; m <<= 1) {
            a00 += shflx(a00, m); a01 += shflx(a01, m);
            a02 += shflx(a02, m); a03 += shflx(a03, m);
            a10 += shflx(a10, m); a11 += shflx(a11, m);
            a12 += shflx(a12, m); a13 += shflx(a13, m);
        }
        if (part == 0) {
            float* dst = &g_Px[(base + r0) * NPX];
            dst[col0]           = a00 + bias0;  dst[col1]           = a10 + bias1;
            dst[NPX + col0]     = a01 + bias0;  dst[NPX + col1]     = a11 + bias1;
            dst[2 * NPX + col0] = a02 + bias0;  dst[2 * NPX + col1] = a12 + bias1;
            dst[3 * NPX + col0] = a03 + bias0;  dst[3 * NPX + col1] = a13 + bias1;
        }
    }
}

// ---------------------------------------------------------------------------
// Kernel 2: sequential recurrence, closed-form probs in y = cos(p) form.
// One warp per batch element; lane = gate*8 + j. R4 structure: EVERY lane
// computes its gate's 5 params itself (no y-broadcast stage -> 2 shfl stages).
//   num = (1+s0 y0)(1+s0 y1)(1+s5 y5)(1+s6 y6)(1+s7 y7)
//   den = 8[(1 + y0 y1) + (y0+y1) y5 y6 y7]
// ---------------------------------------------------------------------------
__global__ void __launch_bounds__(32) qlstm_kernel(
    const float* __restrict__ Wf, const float* __restrict__ Wi,
    const float* __restrict__ Wu, const float* __restrict__ Wo,
    float* __restrict__ out)
{
    const int b    = blockIdx.x;
    const int lane = threadIdx.x;
    const int g    = lane >> 3;
    const int j    = lane & 7;

    const int  v5 = (j >> 2) & 1, v6 = (j >> 1) & 1, v7 = j & 1;
    const float s0 = v7 ? -1.f : 1.f;
    const float s5 = v5 ? -1.f : 1.f;
    const float s6 = (v5 ^ v6) ? -1.f : 1.f;
    const float s7 = (v6 ^ v7) ? -1.f : 1.f;

    const float* Wg = (g == 0) ? Wf : (g == 1) ? Wi : (g == 2) ? Wu : Wo;
    const int qlist[5] = {0, 1, 5, 6, 7};

    // every lane holds its gate's full 5x8 recurrent weight block
    float wh[5][8];
#pragma unroll
    for (int i = 0; i < 5; i++)
#pragma unroll
        for (int jj = 0; jj < 8; jj++)
            wh[i][jj] = Wg[qlist[i] * FAN + DIN + jj];

    // padded px: row stride NPX=32, this gate's 5 slots at g*8 (16B aligned)
    const float* pxbase = &g_Px[(long)b * NPX + g * 8];
    const long   sstride = (long)BATCH * NPX;

    float h = 0.f, c = 0.f;
    float px0[5], px1[5];
    {
        const float4 v0 = *(const float4*)pxbase;
        px0[0]=v0.x; px0[1]=v0.y; px0[2]=v0.z; px0[3]=v0.w; px0[4]=pxbase[4];
        const float4 v1 = *(const float4*)(pxbase + sstride);
        px1[0]=v1.x; px1[1]=v1.y; px1[2]=v1.z; px1[3]=v1.w; px1[4]=(pxbase + sstride)[4];
    }

#pragma unroll 2
    for (int s = 0; s < S_LEN; s++) {
        // prefetch step s+2: ONE float4 + ONE scalar LDG
        float px2[5];
        {
            const int sp = (s + 2 < S_LEN) ? s + 2 : S_LEN - 1;
            const float* pp = pxbase + (long)sp * sstride;
            const float4 v = *(const float4*)pp;
            px2[0]=v.x; px2[1]=v.y; px2[2]=v.z; px2[3]=v.w; px2[4]=pp[4];
        }

        // stage 1: broadcast h
        float hs[8];
#pragma unroll
        for (int jj = 0; jj < 8; jj++) hs[jj] = shfl(h, jj);

        // 5 params for this lane's gate; two FMA chains each
        float y[5];
#pragma unroll
        for (int i = 0; i < 5; i++) {
            float pa = px0[i], pb = 0.f;
            pa = fmaf(wh[i][0], hs[0], pa);
            pa = fmaf(wh[i][1], hs[1], pa);
            pa = fmaf(wh[i][2], hs[2], pa);
            pa = fmaf(wh[i][3], hs[3], pa);
            pb = fmaf(wh[i][4], hs[4], pb);
            pb = fmaf(wh[i][5], hs[5], pb);
            pb = fmaf(wh[i][6], hs[6], pb);
            pb = fmaf(wh[i][7], hs[7], pb);
            y[i] = __cosf(pa + pb);
        }

        const float A   = fmaf(s0, y[0], 1.f) * fmaf(s0, y[1], 1.f);
        const float num = (A * fmaf(s5, y[2], 1.f)) * (fmaf(s6, y[3], 1.f) * fmaf(s7, y[4], 1.f));
        float den = fmaf(y[0] + y[1], (y[2] * y[3]) * y[4], fmaf(y[0], y[1], 1.f));
        den = fmaxf(8.0f * den, 1e-30f);
        const float prob = __fdividef(num, den);

        // stage 2: gather the 4 gate probabilities for this lane's qubit j
        const float pf = shfl(prob, j);
        const float pi = shfl(prob, 8 + j);
        const float pu = shfl(prob, 16 + j);
        const float po = shfl(prob, 24 + j);

        const float gg = ftanh(pu);                 // MUFU.TANH
        c = fmaf(pf, c, pi * gg);
        h = po * ftanh(c);                          // MUFU.TANH

        if (lane < NQ)
            out[(long)s * (BATCH * NQ) + b * NQ + lane] = h;

#pragma unroll
        for (int i = 0; i < 5; i++) { px0[i] = px1[i]; px1[i] = px2[i]; }
    }

    if (lane < NQ) {
        const long ob = (long)S_LEN * BATCH * NQ;
        out[ob + b * NQ + lane] = h;                    // h_n
        out[ob + BATCH * NQ + b * NQ + lane] = c;       // c_n
    }
}

// ---------------------------------------------------------------------------
extern "C" void kernel_launch(void* const* d_in, const int* in_sizes, int n_in,
                              void* d_out, int out_size)
{
    const float* x  = (const float*)d_in[0];
    const float* Wf = (const float*)d_in[1];
    const float* bf = (const float*)d_in[2];
    const float* Wi = (const float*)d_in[3];
    const float* bi = (const float*)d_in[4];
    const float* Wu = (const float*)d_in[5];
    const float* bu = (const float*)d_in[6];
    const float* Wo = (const float*)d_in[7];
    const float* bo = (const float*)d_in[8];
    float* out = (float*)d_out;

    px_kernel<<<2048, 160>>>(x, Wf, bf, Wi, bi, Wu, bu, Wo, bo);
    qlstm_kernel<<<BATCH, 32>>>(Wf, Wi, Wu, Wo, out);
}

// round 8
// speedup vs baseline: 1.3451x; 1.3451x over previous
#include <cuda_runtime.h>
#include <math.h>

#define S_LEN 1024
#define BATCH 128
#define DIN 256
#define NQ 8
#define FAN 264      // DIN + NQ
#define NPX 20       // 4 gates * 5 needed params (q in {0,1,5,6,7})

#define Q_BLOCKS   128            // consumer blocks (one per batch element)
#define PX_BLOCKS  256            // producer blocks
#define ROWS_PER_EPOCH 1024       // PX_BLOCKS * 4 rows
#define N_EPOCH    128            // S_LEN*BATCH / ROWS_PER_EPOCH; 8 s-slices/epoch

// precomputed x-part of gate pre-activations, S-MAJOR: [s][b][20]
__device__ float g_Px[S_LEN * BATCH * NPX];
// epoch completion counters; CUMULATIVE across graph replays (see notes above)
__device__ int g_done[N_EPOCH];

#define FULLMASK 0xffffffffu
__device__ __forceinline__ float shfl(float v, int src) { return __shfl_sync(FULLMASK, v, src); }
__device__ __forceinline__ float shflx(float v, int m)  { return __shfl_xor_sync(FULLMASK, v, m); }

// Hardware tanh: single MUFU instruction (sm_75+).
__device__ __forceinline__ float ftanh(float v) {
    float r;
    asm("tanh.approx.f32 %0, %1;" : "=f"(r) : "f"(v));
    return r;
}

__device__ __forceinline__ int ld_acq(const int* p) {
    int v;
    asm volatile("ld.acquire.gpu.global.b32 %0, [%1];" : "=r"(v) : "l"(p) : "memory");
    return v;
}

// ---------------------------------------------------------------------------
// Producer role: Px[s,b,g*5+qi] = x[s,b,:] . W_g[q,:256] + b_g[q], q in {0,1,5,6,7}
// 160 threads = 20 outputs x 8 k-parts; 4 rows per epoch-iteration.
// Epoch k: px block p handles rows [k*1024 + 4p, +4). After each epoch iter,
// fence + atomicAdd to g_done[k].
// ---------------------------------------------------------------------------
__device__ void px_role(
    int p,
    const float* __restrict__ x,
    const float* __restrict__ W0, const float* __restrict__ B0,
    const float* __restrict__ W1, const float* __restrict__ B1,
    const float* __restrict__ W2, const float* __restrict__ B2,
    const float* __restrict__ W3, const float* __restrict__ B3)
{
    __shared__ float xsh[4 * 256];
    const int t    = threadIdx.x;
    const int og   = t >> 3;       // 0..19
    const int part = t & 7;        // k-slice = jj*8 + part
    const int g    = og / 5;
    const int qi   = og % 5;
    const int q    = (qi == 0) ? 0 : (qi == 1) ? 1 : (qi == 2) ? 5 : (qi == 3) ? 6 : 7;

    const float* Wp[4] = {W0, W1, W2, W3};
    const float* Bp[4] = {B0, B1, B2, B3};
    const float* Wr = Wp[g] + q * FAN;

    float w[32];
#pragma unroll
    for (int jj = 0; jj < 32; jj++) w[jj] = Wr[jj * 8 + part];
    const float bias = Bp[g][q];

    for (int k = 0; k < N_EPOCH; k++) {
        const long row0 = (long)k * ROWS_PER_EPOCH + 4 * p;

        __syncthreads();
        const float4* src = (const float4*)(x + row0 * DIN);
        for (int i = t; i < 256; i += 160) ((float4*)xsh)[i] = src[i];
        __syncthreads();

        float a0 = 0.f, a1 = 0.f, a2 = 0.f, a3 = 0.f;
#pragma unroll
        for (int jj = 0; jj < 32; jj++) {
            const int kk = jj * 8 + part;
            a0 = fmaf(w[jj], xsh[kk],       a0);
            a1 = fmaf(w[jj], xsh[256 + kk], a1);
            a2 = fmaf(w[jj], xsh[512 + kk], a2);
            a3 = fmaf(w[jj], xsh[768 + kk], a3);
        }
#pragma unroll
        for (int m = 1; m < 8; m <<= 1) {
            a0 += shflx(a0, m); a1 += shflx(a1, m);
            a2 += shflx(a2, m); a3 += shflx(a3, m);
        }
        if (part == 0) {
            float* dst = &g_Px[row0 * NPX + og];
            dst[0]       = a0 + bias;
            dst[NPX]     = a1 + bias;
            dst[2 * NPX] = a2 + bias;
            dst[3 * NPX] = a3 + bias;
        }

        __syncthreads();                    // all writes of this iter done
        if (t == 0) {
            __threadfence();                // make g_Px visible before flag
            atomicAdd(&g_done[k], 1);
        }
    }
}

// ---------------------------------------------------------------------------
// Consumer role: sequential recurrence (R6 structure: 1 param per lane,
// 3 shfl stages, closed-form probs in y = cos(p) form).
//   num = (1+s0 y0)(1+s0 y1)(1+s5 y5)(1+s6 y6)(1+s7 y7)
//   den = 8[(1 + y0 y1) + (y0+y1) y5 y6 y7]
// ---------------------------------------------------------------------------
__device__ void qlstm_role(
    int b,
    const float* __restrict__ Wf, const float* __restrict__ Wi,
    const float* __restrict__ Wu, const float* __restrict__ Wo,
    float* __restrict__ out)
{
    const int lane = threadIdx.x;           // 0..31 (threads >=32 returned)
    const int g    = lane >> 3;
    const int i    = lane & 7;              // param slot (i<5) and qubit j
    const int gb   = lane & 24;

    const int  v5 = (i >> 2) & 1, v6 = (i >> 1) & 1, v7 = i & 1;
    const float s0 = v7 ? -1.f : 1.f;
    const float s5 = v5 ? -1.f : 1.f;
    const float s6 = (v5 ^ v6) ? -1.f : 1.f;
    const float s7 = (v6 ^ v7) ? -1.f : 1.f;

    const float* Wg = (g == 0) ? Wf : (g == 1) ? Wi : (g == 2) ? Wu : Wo;
    const int q = (i == 0) ? 0 : (i == 1) ? 1 : (i == 2) ? 5 : (i == 3) ? 6 : 7;
    const bool par = (i < 5);

    float wh[8];
#pragma unroll
    for (int jj = 0; jj < 8; jj++)
        wh[jj] = par ? Wg[q * FAN + DIN + jj] : 0.f;

    // wait for epoch 0 (covers s-slices 0..7) before the initial loads
    while (ld_acq(&g_done[0]) < PX_BLOCKS) {}
    int kcur = 0;

    const int poff = g * 5 + i;
    float h = 0.f, c = 0.f;
    float px0 = par ? g_Px[(long)b * NPX + poff] : 0.f;                  // s=0
    float px1 = par ? g_Px[((long)BATCH + b) * NPX + poff] : 0.f;        // s=1

#pragma unroll 2
    for (int s = 0; s < S_LEN; s++) {
        // gate the prefetch of step s+2 on its epoch (poll once per 8 steps)
        const int sp = (s + 2 < S_LEN) ? s + 2 : S_LEN - 1;
        const int kn = sp >> 3;
        if (kn > kcur) {
            while (ld_acq(&g_done[kn]) < PX_BLOCKS) {}
            kcur = kn;
        }
        float px2 = 0.f;
        if (par) px2 = g_Px[((long)sp * BATCH + b) * NPX + poff];

        // stage 1: broadcast h
        const float hs0 = shfl(h, 0), hs1 = shfl(h, 1), hs2 = shfl(h, 2), hs3 = shfl(h, 3);
        const float hs4 = shfl(h, 4), hs5 = shfl(h, 5), hs6 = shfl(h, 6), hs7 = shfl(h, 7);

        // one param per lane: two short FMA chains
        float pa = fmaf(wh[0], hs0, px0);
        pa = fmaf(wh[1], hs1, pa);
        pa = fmaf(wh[2], hs2, pa);
        pa = fmaf(wh[3], hs3, pa);
        float pb = wh[4] * hs4;
        pb = fmaf(wh[5], hs5, pb);
        pb = fmaf(wh[6], hs6, pb);
        pb = fmaf(wh[7], hs7, pb);
        const float y = __cosf(pa + pb);

        // stage 2: broadcast the gate's 5 y values within the group
        const float y0 = shfl(y, gb + 0);
        const float y1 = shfl(y, gb + 1);
        const float y5 = shfl(y, gb + 2);
        const float y6 = shfl(y, gb + 3);
        const float y7 = shfl(y, gb + 4);

        const float A   = fmaf(s0, y0, 1.f) * fmaf(s0, y1, 1.f);
        const float num = (A * fmaf(s5, y5, 1.f)) * (fmaf(s6, y6, 1.f) * fmaf(s7, y7, 1.f));
        float den = fmaf(y0 + y1, (y5 * y6) * y7, fmaf(y0, y1, 1.f));
        den = fmaxf(8.0f * den, 1e-30f);
        const float prob = __fdividef(num, den);

        // stage 3: gather the 4 gate probabilities for qubit j = i
        const float pf = shfl(prob, i);
        const float pi = shfl(prob, 8 + i);
        const float pu = shfl(prob, 16 + i);
        const float po = shfl(prob, 24 + i);

        const float gg = ftanh(pu);                 // MUFU.TANH
        c = fmaf(pf, c, pi * gg);
        h = po * ftanh(c);                          // MUFU.TANH

        if (lane < NQ)
            out[(long)s * (BATCH * NQ) + b * NQ + lane] = h;

        px0 = px1; px1 = px2;
    }

    if (lane < NQ) {
        const long ob = (long)S_LEN * BATCH * NQ;
        out[ob + b * NQ + lane] = h;                    // h_n
        out[ob + BATCH * NQ + b * NQ + lane] = c;       // c_n
    }
}

// ---------------------------------------------------------------------------
// Fused kernel: blocks 0..127 = consumers, blocks 128..383 = producers.
// All 384 blocks are wave-1 resident (384*160 threads, <=80 regs) -> no deadlock.
// ---------------------------------------------------------------------------
__global__ void __launch_bounds__(160) qlstm_fused_kernel(
    const float* __restrict__ x,
    const float* __restrict__ W0, const float* __restrict__ B0,
    const float* __restrict__ W1, const float* __restrict__ B1,
    const float* __restrict__ W2, const float* __restrict__ B2,
    const float* __restrict__ W3, const float* __restrict__ B3,
    float* __restrict__ out)
{
    if (blockIdx.x < Q_BLOCKS) {
        if (threadIdx.x >= 32) return;      // consumer path: warp 0 only, no bars
        qlstm_role(blockIdx.x, W0, W1, W2, W3, out);
    } else {
        px_role(blockIdx.x - Q_BLOCKS, x, W0, B0, W1, B1, W2, B2, W3, B3);
    }
}

// ---------------------------------------------------------------------------
extern "C" void kernel_launch(void* const* d_in, const int* in_sizes, int n_in,
                              void* d_out, int out_size)
{
    const float* x  = (const float*)d_in[0];
    const float* Wf = (const float*)d_in[1];
    const float* bf = (const float*)d_in[2];
    const float* Wi = (const float*)d_in[3];
    const float* bi = (const float*)d_in[4];
    const float* Wu = (const float*)d_in[5];
    const float* bu = (const float*)d_in[6];
    const float* Wo = (const float*)d_in[7];
    const float* bo = (const float*)d_in[8];
    float* out = (float*)d_out;

    qlstm_fused_kernel<<<Q_BLOCKS + PX_BLOCKS, 160>>>(
        x, Wf, bf, Wi, bi, Wu, bu, Wo, bo, out);
}